// round 17
// baseline (speedup 1.0000x reference)
#include <cuda_runtime.h>
#include <cuda_fp16.h>
#include <cstdint>

// ---------------- problem constants ----------------
#define B_    8
#define C_    1024       // INPUT_DIM
#define HW_   4096       // H*W
#define L_    4096       // sequence length = H*W
#define D_    1024       // DIM
#define N_    256        // N_SLOTS
#define MLP_  512        // MLP_DIM
#define TITER 6
#define EPS_  1e-5f
#define SCALE_ 0.03125f  // DIM^-0.5
#define SPLK  2          // split-K factor for update GEMM

// ---------------- scratch (device globals; no allocation allowed) ----------------
__device__ float g_tmpl[B_*N_*D_];                 // fp32 residual stream
__device__ float g_cspart[B_*32*N_];
__device__ float g_csinv[B_*N_];
__device__ float g_part[(size_t)SPLK*B_*N_*D_];    // split-K partials (16 MB)

__device__ __half g_xn_h [(size_t)B_*L_*C_];       // 64 MB
__device__ __half g_k_h  [(size_t)B_*L_*D_];       // 64 MB
__device__ __half g_vT_h [(size_t)B_*D_*L_];       // 64 MB
__device__ __half g_attnT_h[(size_t)B_*N_*L_];     // 16 MB
__device__ __half g_q_h  [B_*N_*D_];
__device__ __half g_t2_h [B_*N_*D_];
__device__ __half g_h_h  [B_*N_*MLP_];
__device__ __half g_WqT_h[D_*D_];
__device__ __half g_WkT_h[D_*C_];
__device__ __half g_WvT_h[D_*C_];
__device__ __half g_W1T_h[MLP_*D_];
__device__ __half g_W2T_h[D_*MLP_];

// ---------------- helpers ----------------
__device__ __forceinline__ uint32_t smem_u32(const void* p) {
    uint32_t a;
    asm("{ .reg .u64 t; cvta.to.shared.u64 t, %1; cvt.u32.u64 %0, t; }" : "=r"(a) : "l"(p));
    return a;
}
__device__ __forceinline__ void cp16(uint32_t s, const void* g) {
    asm volatile("cp.async.cg.shared.global [%0], [%1], 16;\n" :: "r"(s), "l"(g));
}
#define CP_COMMIT() asm volatile("cp.async.commit_group;\n" ::: "memory")
#define CP_WAIT(N)  asm volatile("cp.async.wait_group %0;\n" :: "n"(N) : "memory")

__device__ __forceinline__ void ldsm4(uint32_t (&r)[4], uint32_t addr) {
    asm volatile("ldmatrix.sync.aligned.m8n8.x4.shared.b16 {%0,%1,%2,%3}, [%4];"
                 : "=r"(r[0]), "=r"(r[1]), "=r"(r[2]), "=r"(r[3]) : "r"(addr));
}
__device__ __forceinline__ void mma16816(float (&c)[4], const uint32_t (&a)[4],
                                         uint32_t b0, uint32_t b1) {
    asm volatile(
        "mma.sync.aligned.m16n8k16.row.col.f32.f16.f16.f32 "
        "{%0,%1,%2,%3}, {%4,%5,%6,%7}, {%8,%9}, {%0,%1,%2,%3};"
        : "+f"(c[0]), "+f"(c[1]), "+f"(c[2]), "+f"(c[3])
        : "r"(a[0]), "r"(a[1]), "r"(a[2]), "r"(a[3]), "r"(b0), "r"(b1));
}

// ================= generic tensor-core GEMM (fp16 mma.sync m16n8k16) =================
// cp.async pipeline (TM=128: 3-stage; TM=64: 4-stage), 1 __syncthreads per K-chunk,
// XOR-swizzled smem. Inner-loop addresses: A0 ^ (ks<<5) with A0 per-chunk (ALU-minimal).
// EPI: 0 alpha*acc | 3 relu(acc+bias) | 4 res+acc+bias
#define KC_ 64
#define TG_SMEM (98304 + 128)    // stages + 128B alignment slack

template<int EPI, int OUTH, int SPLITK, int OUTT, int TM>
__global__ void __launch_bounds__(256, 2)
tgemm(const __half* __restrict__ A, const __half* __restrict__ Bm,
      void* __restrict__ Cv, int Kld, int Klen, int ldc,
      long long sA, long long sB, long long sC,
      const float* __restrict__ res, const float* __restrict__ bias, float alpha) {
    constexpr int NF = (TM == 128) ? 8 : 4;     // n8 fragments per warp
    constexpr int NP = NF / 2;                  // n16 ldmatrix groups per warp
    constexpr int A_BYTES = TM * 128;
    constexpr int STAGE = A_BYTES + 16384;
    constexpr int STAGES = (TM == 128) ? 3 : 4;

    extern __shared__ __half sh[];
    const uint32_t su = (smem_u32(sh) + 127u) & ~127u;   // 128-aligned base

    const int tid  = threadIdx.x;
    const int wid  = tid >> 5;
    const int lane = tid & 31;
    const int wm = (TM == 128) ? (wid >> 1) * 32 : (wid >> 2) * 32;
    const int wn = (TM == 128) ? (wid & 1) * 64 : (wid & 3) * 32;

    const int z = blockIdx.z;
    const int bz = (SPLITK > 1) ? z / SPLITK : z;
    const int sk = (SPLITK > 1) ? z % SPLITK : 0;
    A  += (size_t)bz * sA + (size_t)sk * Klen;
    Bm += (size_t)bz * sB + (size_t)sk * Klen;
    float*  Cf;
    __half* Ch = (__half*)Cv;
    if (SPLITK > 1) Cf = (float*)Cv + (size_t)z * sC;
    else            Cf = (float*)Cv + (OUTH ? 0 : (size_t)bz * sC);
    if (OUTH && !OUTT) Ch = (__half*)Cv + (size_t)bz * sC;
    if (EPI == 4) res += (size_t)bz * sC;

    const int m0 = blockIdx.y * TM;
    const int n0 = blockIdx.x * 128;
    const __half* gA = A + (size_t)m0 * Kld;
    const __half* gB = Bm + (size_t)n0 * Kld;

    float acc[2][NF][4];
    #pragma unroll
    for (int i = 0; i < 2; i++)
        #pragma unroll
        for (int j = 0; j < NF; j++)
            #pragma unroll
            for (int r = 0; r < 4; r++) acc[i][j][r] = 0.f;

    // swizzled store offset for (row, chunk[16B]): row*128 + ((ch ^ (row&7))<<4)
    auto load_chunk = [&](int c) {
        uint32_t st = su + (uint32_t)((c % STAGES) * STAGE);
        const __half* ga = gA + c * KC_;
        const __half* gb = gB + c * KC_;
        #pragma unroll
        for (int i = 0; i < TM / 32; i++) {
            int e = tid + i * 256;
            int row = e >> 3;
            int ch = e & 7;
            uint32_t so = (uint32_t)(row * 128 + ((ch ^ (row & 7)) << 4));
            cp16(st + so, ga + (size_t)row * Kld + ch * 8);
        }
        #pragma unroll
        for (int i = 0; i < 4; i++) {
            int e = tid + i * 256;
            int row = e >> 3;
            int ch = e & 7;
            uint32_t so = (uint32_t)(row * 128 + ((ch ^ (row & 7)) << 4));
            cp16(st + (uint32_t)A_BYTES + so, gb + (size_t)row * Kld + ch * 8);
        }
        CP_COMMIT();
    };

    const int NC = Klen / KC_;   // >= 8 always
    load_chunk(0);
    load_chunk(1);
    if (STAGES == 4) load_chunk(2);

    const int rsel = (lane & 7) + ((lane >> 3) & 1) * 8;
    const int kbit = (lane >> 4) & 1;
    // per-fragment swizzle-folded offsets: addr(ks) = (base + po) ^ (ks<<5)
    uint32_t poA[2], poB[NP];
    #pragma unroll
    for (int mf = 0; mf < 2; mf++) {
        int r = wm + mf * 16 + rsel;
        poA[mf] = (uint32_t)(r * 128 + ((kbit ^ (r & 7)) << 4));
    }
    #pragma unroll
    for (int np = 0; np < NP; np++) {
        int r = wn + np * 16 + rsel;
        poB[np] = (uint32_t)(r * 128 + ((kbit ^ (r & 7)) << 4));
    }

    for (int c = 0; c < NC; c++) {
        if (STAGES == 4) CP_WAIT(2); else CP_WAIT(1);
        __syncthreads();
        if (c + STAGES - 1 < NC) load_chunk(c + STAGES - 1); else CP_COMMIT();

        uint32_t abase = su + (uint32_t)((c % STAGES) * STAGE);
        uint32_t bbase = abase + (uint32_t)A_BYTES;
        uint32_t aadr[2], badr[NP];
        #pragma unroll
        for (int mf = 0; mf < 2; mf++) aadr[mf] = abase + poA[mf];
        #pragma unroll
        for (int np = 0; np < NP; np++) badr[np] = bbase + poB[np];

        #pragma unroll
        for (int ks = 0; ks < 4; ks++) {
            const uint32_t kx = (uint32_t)(ks << 5);
            uint32_t a[2][4];
            #pragma unroll
            for (int mf = 0; mf < 2; mf++)
                ldsm4(a[mf], aadr[mf] ^ kx);
            uint32_t b[NP][4];
            #pragma unroll
            for (int np = 0; np < NP; np++)
                ldsm4(b[np], badr[np] ^ kx);
            #pragma unroll
            for (int mf = 0; mf < 2; mf++)
                #pragma unroll
                for (int nf = 0; nf < NF; nf++)
                    mma16816(acc[mf][nf], a[mf], b[nf >> 1][nf & 1], b[nf >> 1][2 + (nf & 1)]);
        }
    }

    if (OUTT) {
        __syncthreads();     // computes done before reusing stage smem
        __half* stg = (__half*)(size_t)0;  // placeholder; use su-based pointer below
        // use raw shared pointer via su for staging
        stg = sh;  // sh region (unaligned base ok for staging layout)
        #pragma unroll
        for (int mf = 0; mf < 2; mf++)
            #pragma unroll
            for (int h = 0; h < 2; h++) {
                int ml = wm + mf * 16 + h * 8 + (lane >> 2);
                #pragma unroll
                for (int nf = 0; nf < NF; nf++) {
                    int nl = wn + nf * 8 + (lane & 3) * 2;
                    stg[nl * 136 + ml]       = __float2half_rn(acc[mf][nf][h * 2 + 0]);
                    stg[(nl + 1) * 136 + ml] = __float2half_rn(acc[mf][nf][h * 2 + 1]);
                }
            }
        __syncthreads();
        int b = m0 >> 12;
        int l0 = m0 & (L_ - 1);
        __half* dst = Ch + (size_t)b * D_ * L_ + (size_t)n0 * L_ + l0;
        int r = tid >> 1, c0 = (tid & 1) * 64;
        const uint4* s4 = (const uint4*)(stg + r * 136 + c0);
        uint4* d4 = (uint4*)(dst + (size_t)r * L_ + c0);
        #pragma unroll
        for (int i = 0; i < 8; i++) d4[i] = s4[i];
        return;
    }

    #pragma unroll
    for (int mf = 0; mf < 2; mf++) {
        #pragma unroll
        for (int h = 0; h < 2; h++) {
            int m = m0 + wm + mf * 16 + h * 8 + (lane >> 2);
            #pragma unroll
            for (int nf = 0; nf < NF; nf++) {
                int n = n0 + wn + nf * 8 + (lane & 3) * 2;
                size_t idx = (size_t)m * ldc + n;
                float v0 = acc[mf][nf][h * 2 + 0];
                float v1 = acc[mf][nf][h * 2 + 1];
                if (EPI == 0)      { v0 *= alpha; v1 *= alpha; }
                else if (EPI == 3) { v0 = fmaxf(v0 + bias[n], 0.f); v1 = fmaxf(v1 + bias[n + 1], 0.f); }
                else if (EPI == 4) { v0 = res[idx] + v0 + bias[n]; v1 = res[idx + 1] + v1 + bias[n + 1]; }
                if (OUTH) *(__half2*)&Ch[idx] = __floats2half2_rn(v0, v1);
                else      *(float2*)&Cf[idx] = make_float2(v0, v1);
            }
        }
    }
}

// ================= fused logits GEMM + softmax + attnT + colsum =================
#define ATROW 40
#define ATSTAGE (384 * ATROW)
#define AT_SMEM (3 * ATSTAGE * 2)  // 92160 bytes

__global__ void __launch_bounds__(256, 1)
attn_gemm() {
    extern __shared__ __half sh[];
    char* sc = (char*)sh;
    const uint32_t su = smem_u32(sh);
    const int tid = threadIdx.x, wid = tid >> 5, lane = tid & 31;
    const int wm = (wid >> 1) * 32, wn = (wid & 1) * 128;
    const int b = blockIdx.z, m0 = blockIdx.y * 128;
    const __half* gA = g_k_h + ((size_t)b * L_ + m0) * D_;
    const __half* gB = g_q_h + (size_t)b * N_ * D_;

    float acc[2][16][4];
    #pragma unroll
    for (int i = 0; i < 2; i++)
        #pragma unroll
        for (int j = 0; j < 16; j++)
            #pragma unroll
            for (int r = 0; r < 4; r++) acc[i][j][r] = 0.f;

    auto load_chunk = [&](int c) {
        uint32_t st = su + (uint32_t)((c % 3) * ATSTAGE) * 2u;
        #pragma unroll
        for (int i = 0; i < 2; i++) {
            int e = tid + i * 256;
            int row = e >> 2, qq = (e & 3) * 8;
            cp16(st + (uint32_t)(row * ATROW + qq) * 2u, gA + (size_t)row * D_ + c * 32 + qq);
        }
        #pragma unroll
        for (int i = 0; i < 4; i++) {
            int e = tid + i * 256;
            int row = e >> 2, qq = (e & 3) * 8;
            cp16(st + (uint32_t)((128 + row) * ATROW + qq) * 2u, gB + (size_t)row * D_ + c * 32 + qq);
        }
        CP_COMMIT();
    };

    const int NC = D_ / 32;
    load_chunk(0);
    load_chunk(1);
    const int rsel = (lane & 7) + ((lane >> 3) & 1) * 8;
    const int ksel = ((lane >> 4) & 1) * 8;

    // per-fragment byte offsets (stage-invariant); per-ks address = base + pa + ks*32
    uint32_t pa[2], pb[8];
    #pragma unroll
    for (int mf = 0; mf < 2; mf++)
        pa[mf] = (uint32_t)(((wm + mf * 16 + rsel) * ATROW + ksel) * 2);
    #pragma unroll
    for (int np = 0; np < 8; np++)
        pb[np] = (uint32_t)(((128 + wn + np * 16 + rsel) * ATROW + ksel) * 2);

    for (int c = 0; c < NC; c++) {
        CP_WAIT(1);
        __syncthreads();
        if (c + 2 < NC) load_chunk(c + 2); else CP_COMMIT();

        uint32_t sbase = su + (uint32_t)((c % 3) * ATSTAGE) * 2u;
        #pragma unroll
        for (int ks = 0; ks < 2; ks++) {
            const uint32_t ko = (uint32_t)(ks * 32);
            uint32_t a[2][4];
            #pragma unroll
            for (int mf = 0; mf < 2; mf++)
                ldsm4(a[mf], sbase + pa[mf] + ko);
            uint32_t bf[8][4];
            #pragma unroll
            for (int np = 0; np < 8; np++)
                ldsm4(bf[np], sbase + pb[np] + ko);
            #pragma unroll
            for (int mf = 0; mf < 2; mf++)
                #pragma unroll
                for (int nf = 0; nf < 16; nf++)
                    mma16816(acc[mf][nf], a[mf], bf[nf >> 1][nf & 1], bf[nf >> 1][2 + (nf & 1)]);
        }
    }
    __syncthreads();

    // ---- softmax epilogue ----
    __half* stg = sh;
    float* redv = (float*)(sc + 69632);
    const int nwh = (wid & 1);
    float mx4[4], inv4[4];

    #pragma unroll
    for (int r = 0; r < 4; r++) {
        int mf = r >> 1, hh = r & 1;
        float m = -1e30f;
        #pragma unroll
        for (int nf = 0; nf < 16; nf++)
            m = fmaxf(m, fmaxf(acc[mf][nf][hh * 2], acc[mf][nf][hh * 2 + 1]));
        m = fmaxf(m, __shfl_xor_sync(0xffffffffu, m, 1));
        m = fmaxf(m, __shfl_xor_sync(0xffffffffu, m, 2));
        if ((lane & 3) == 0)
            redv[nwh * 128 + wm + mf * 16 + hh * 8 + (lane >> 2)] = m;
    }
    __syncthreads();
    #pragma unroll
    for (int r = 0; r < 4; r++) {
        int rowl = wm + (r >> 1) * 16 + (r & 1) * 8 + (lane >> 2);
        mx4[r] = fmaxf(redv[rowl], redv[128 + rowl]);
    }
    __syncthreads();
    #pragma unroll
    for (int r = 0; r < 4; r++) {
        int mf = r >> 1, hh = r & 1;
        float s = 0.f;
        #pragma unroll
        for (int nf = 0; nf < 16; nf++) {
            float e0 = __expf(acc[mf][nf][hh * 2]     - mx4[r]);
            float e1 = __expf(acc[mf][nf][hh * 2 + 1] - mx4[r]);
            acc[mf][nf][hh * 2] = e0; acc[mf][nf][hh * 2 + 1] = e1;
            s += e0 + e1;
        }
        s += __shfl_xor_sync(0xffffffffu, s, 1);
        s += __shfl_xor_sync(0xffffffffu, s, 2);
        if ((lane & 3) == 0)
            redv[nwh * 128 + wm + mf * 16 + hh * 8 + (lane >> 2)] = s;
    }
    __syncthreads();
    #pragma unroll
    for (int r = 0; r < 4; r++) {
        int rowl = wm + (r >> 1) * 16 + (r & 1) * 8 + (lane >> 2);
        inv4[r] = 1.f / (redv[rowl] + redv[128 + rowl]);
    }
    #pragma unroll
    for (int r = 0; r < 4; r++) {
        int mf = r >> 1, hh = r & 1;
        int rowl = wm + mf * 16 + hh * 8 + (lane >> 2);
        #pragma unroll
        for (int nf = 0; nf < 16; nf++) {
            float p0 = acc[mf][nf][hh * 2]     * inv4[r] + 1e-8f;
            float p1 = acc[mf][nf][hh * 2 + 1] * inv4[r] + 1e-8f;
            int col = wn + nf * 8 + (lane & 3) * 2;
            stg[col * 136 + rowl]       = __float2half_rn(p0);
            stg[(col + 1) * 136 + rowl] = __float2half_rn(p1);
        }
    }
    __syncthreads();
    {
        float cs = 0.f;
        const uint4* s4 = (const uint4*)(stg + tid * 136);
        uint4* d4 = (uint4*)(g_attnT_h + ((size_t)b * N_ + tid) * L_ + m0);
        #pragma unroll
        for (int j = 0; j < 16; j++) {
            uint4 u = s4[j];
            d4[j] = u;
            const __half2* hp = (const __half2*)&u;
            #pragma unroll
            for (int t = 0; t < 4; t++) {
                float2 f = __half22float2(hp[t]);
                cs += f.x + f.y;
            }
        }
        g_cspart[((size_t)b * 32 + blockIdx.y) * N_ + tid] = cs;
    }
}

// ---------------- block reduction ----------------
__device__ __forceinline__ float block_sum(float v) {
    __shared__ float shm[8];
    __shared__ float tot;
    #pragma unroll
    for (int o = 16; o; o >>= 1) v += __shfl_xor_sync(0xffffffffu, v, o);
    if ((threadIdx.x & 31) == 0) shm[threadIdx.x >> 5] = v;
    __syncthreads();
    if (threadIdx.x == 0) {
        float s = 0.f;
        #pragma unroll
        for (int i = 0; i < 8; i++) s += shm[i];
        tot = s;
    }
    __syncthreads();
    return tot;
}

// ---- fused: colsum finalize + split-K reduce + residual + LayerNorm(lm) -> t2 half ----
__global__ void update_ln(const float* __restrict__ gam, const float* __restrict__ bet) {
    int row = blockIdx.x;
    int b = row >> 8, n = row & (N_ - 1);
    int t = threadIdx.x;
    float cp = (t < 32) ? g_cspart[((size_t)b * 32 + t) * N_ + n] : 0.f;
    float tot = block_sum(cp);
    float inv = 1.f / tot;
    if (t == 0) g_csinv[row] = inv;
    size_t eb = (size_t)row * 1024 + t * 4;
    float4 u = *(const float4*)&g_tmpl[eb];
    float4 ps = make_float4(0.f, 0.f, 0.f, 0.f);
    #pragma unroll
    for (int sk = 0; sk < SPLK; sk++) {
        float4 pp = *(const float4*)&g_part[((size_t)(b * SPLK + sk) * N_ + n) * 1024 + t * 4];
        ps.x += pp.x; ps.y += pp.y; ps.z += pp.z; ps.w += pp.w;
    }
    u.x += inv * ps.x; u.y += inv * ps.y; u.z += inv * ps.z; u.w += inv * ps.w;
    float s1 = block_sum(u.x + u.y + u.z + u.w);
    float mu = s1 * (1.f / 1024.f);
    float dx = u.x - mu, dy = u.y - mu, dz = u.z - mu, dw = u.w - mu;
    float ss = block_sum(dx*dx + dy*dy + dz*dz + dw*dw);
    float rs = rsqrtf(ss * (1.f / 1024.f) + EPS_);
    *(float4*)&g_tmpl[eb] = u;
    float4 g4 = ((const float4*)gam)[t];
    float4 b4 = ((const float4*)bet)[t];
    __half2* o = (__half2*)(g_t2_h + (size_t)row * 1024);
    o[t * 2 + 0] = __floats2half2_rn(dx * rs * g4.x + b4.x, dy * rs * g4.y + b4.y);
    o[t * 2 + 1] = __floats2half2_rn(dz * rs * g4.z + b4.z, dw * rs * g4.w + b4.w);
}

// ================= non-GEMM kernels =================
// fused input LN: stats (pass 1) + transpose+normalize (pass 2, L2-resident re-read)
__global__ void norm_input(const float* __restrict__ x,
                           const float* __restrict__ gamma,
                           const float* __restrict__ beta) {
    __shared__ float S[8][33], SS[8][33];
    __shared__ float MU[32], RS[32];
    __shared__ float tile[32][33];
    int b = blockIdx.y, l0 = blockIdx.x * 32;
    int tx = threadIdx.x, ty = threadIdx.y;
    const float* xb = x + (size_t)b * C_ * HW_ + l0;
    float s = 0.f, ss = 0.f;
    for (int c = ty; c < C_; c += 8) {
        float v = xb[(size_t)c * HW_ + tx];
        s += v; ss += v * v;
    }
    S[ty][tx] = s; SS[ty][tx] = ss;
    __syncthreads();
    if (ty == 0) {
        float a = 0.f, b2 = 0.f;
        #pragma unroll
        for (int i = 0; i < 8; i++) { a += S[i][tx]; b2 += SS[i][tx]; }
        float mu = a * (1.f / C_);
        float var = b2 * (1.f / C_) - mu * mu;
        MU[tx] = mu;
        RS[tx] = rsqrtf(fmaxf(var, 0.f) + EPS_);
    }
    __syncthreads();
    for (int c0 = 0; c0 < C_; c0 += 32) {
        #pragma unroll
        for (int r = 0; r < 4; r++)
            tile[ty + 8*r][tx] = xb[(size_t)(c0 + ty + 8*r) * HW_ + tx];
        __syncthreads();
        #pragma unroll
        for (int r = 0; r < 4; r++) {
            int lr = ty + 8*r;
            int c = c0 + tx;
            g_xn_h[((size_t)(b * L_ + l0 + lr)) * C_ + c] =
                __float2half_rn((tile[tx][lr] - MU[lr]) * RS[lr] * gamma[c] + beta[c]);
        }
        __syncthreads();
    }
}

// one tiled-transpose unit: in[R x C] -> out[C x R], tile index (br, bc)
__device__ __forceinline__ void tw_tile(const float* __restrict__ in, __half* __restrict__ out,
                                        int R, int Ccols, int br, int bc,
                                        int tx, int ty) {
    __shared__ float tile[32][33];
    int r0 = br * 32, c0 = bc * 32;
    #pragma unroll
    for (int i = 0; i < 4; i++)
        tile[ty + 8*i][tx] = in[(size_t)(r0 + ty + 8*i) * Ccols + c0 + tx];
    __syncthreads();
    #pragma unroll
    for (int i = 0; i < 4; i++)
        out[(size_t)(c0 + ty + 8*i) * R + r0 + tx] = __float2half_rn(tile[tx][ty + 8*i]);
}

// combined one-time prep: 5 weight transposes + template broadcast (segmented grid)
__global__ void prep_all(const float* __restrict__ Wq, const float* __restrict__ Wk,
                         const float* __restrict__ Wv, const float* __restrict__ W1,
                         const float* __restrict__ W2, const float* __restrict__ ti) {
    int bx = blockIdx.x;
    int tx = threadIdx.x, ty = threadIdx.y;
    if (bx < 1024) {                     // Wq [1024,1024]
        tw_tile(Wq, g_WqT_h, D_, D_, bx >> 5, bx & 31, tx, ty);
    } else if (bx < 2048) {              // Wk [1024,1024]
        int i = bx - 1024;
        tw_tile(Wk, g_WkT_h, C_, D_, i >> 5, i & 31, tx, ty);
    } else if (bx < 3072) {              // Wv [1024,1024]
        int i = bx - 2048;
        tw_tile(Wv, g_WvT_h, C_, D_, i >> 5, i & 31, tx, ty);
    } else if (bx < 3584) {              // W1 [1024,512]
        int i = bx - 3072;
        tw_tile(W1, g_W1T_h, D_, MLP_, i >> 4, i & 15, tx, ty);
    } else if (bx < 4096) {              // W2 [512,1024]
        int i = bx - 3584;
        tw_tile(W2, g_W2T_h, MLP_, D_, i >> 5, i & 31, tx, ty);
    } else {                             // bcast templates
        int i = (bx - 4096) * 256 + ty * 32 + tx;
        g_tmpl[i] = ti[i & (N_ * D_ - 1)];
    }
}

__global__ void ln_rows(const float* __restrict__ in, __half* __restrict__ out,
                        const float* __restrict__ gamma, const float* __restrict__ beta) {
    int row = blockIdx.x;
    int t = threadIdx.x;
    float4 v = ((const float4*)(in + (size_t)row * 1024))[t];
    float s = block_sum(v.x + v.y + v.z + v.w);
    float mu = s * (1.f / 1024.f);
    float dx = v.x - mu, dy = v.y - mu, dz = v.z - mu, dw = v.w - mu;
    float ss = block_sum(dx*dx + dy*dy + dz*dz + dw*dw);
    float rs = rsqrtf(ss * (1.f / 1024.f) + EPS_);
    float4 g4 = ((const float4*)gamma)[t];
    float4 b4 = ((const float4*)beta)[t];
    __half2* orow = (__half2*)(out + (size_t)row * 1024);
    orow[t * 2 + 0] = __floats2half2_rn(dx * rs * g4.x + b4.x, dy * rs * g4.y + b4.y);
    orow[t * 2 + 1] = __floats2half2_rn(dz * rs * g4.z + b4.z, dw * rs * g4.w + b4.w);
}

// combined outputs: blocks [0,2048) -> templates transpose; rest -> attn scale copy
__global__ void out_all(float* __restrict__ out_t, float* __restrict__ out_a) {
    int bx = blockIdx.x;
    int tx = threadIdx.x, ty = threadIdx.y;
    if (bx < 2048) {
        __shared__ float tile[32][33];
        int n0 = (bx & 7) * 32, d0 = ((bx >> 3) & 31) * 32, b = bx >> 8;
        const float* tp = g_tmpl + (size_t)b * N_ * D_;
        #pragma unroll
        for (int r = 0; r < 4; r++)
            tile[ty + 8*r][tx] = tp[(size_t)(n0 + ty + 8*r) * D_ + d0 + tx];
        __syncthreads();
        float* op = out_t + (size_t)b * D_ * N_;
        #pragma unroll
        for (int r = 0; r < 4; r++)
            op[(size_t)(d0 + ty + 8*r) * N_ + n0 + tx] = tile[tx][ty + 8*r];
    } else {
        size_t i = (size_t)(bx - 2048) * 256 + ty * 32 + tx;
        out_a[i] = __half2float(g_attnT_h[i]) * g_csinv[i >> 12];
    }
}

// ================= launch =================
extern "C" void kernel_launch(void* const* d_in, const int* in_sizes, int n_in,
                              void* d_out, int out_size) {
    const float* x      = (const float*)d_in[0];
    const float* ti     = (const float*)d_in[1];
    const float* Wq     = (const float*)d_in[2];
    const float* Wk     = (const float*)d_in[3];
    const float* Wv     = (const float*)d_in[4];
    const float* lin_g  = (const float*)d_in[5];
    const float* lin_b  = (const float*)d_in[6];
    const float* lt_g   = (const float*)d_in[7];
    const float* lt_b   = (const float*)d_in[8];
    const float* lm_g   = (const float*)d_in[9];
    const float* lm_b   = (const float*)d_in[10];
    const float* W1     = (const float*)d_in[11];
    const float* b1     = (const float*)d_in[12];
    const float* W2     = (const float*)d_in[13];
    const float* b2     = (const float*)d_in[14];
    float* out_t = (float*)d_out;                          // [B, D, N]
    float* out_a = (float*)d_out + (size_t)B_ * D_ * N_;   // [B, N, H, W]

    float *p_tmpl, *p_part;
    __half *p_xn, *p_k, *p_vT, *p_attnT, *p_q, *p_t2, *p_h;
    __half *p_WqT, *p_WkT, *p_WvT, *p_W1T, *p_W2T;
    cudaGetSymbolAddress((void**)&p_tmpl, g_tmpl);
    cudaGetSymbolAddress((void**)&p_part, g_part);
    cudaGetSymbolAddress((void**)&p_xn, g_xn_h);
    cudaGetSymbolAddress((void**)&p_k, g_k_h);
    cudaGetSymbolAddress((void**)&p_vT, g_vT_h);
    cudaGetSymbolAddress((void**)&p_attnT, g_attnT_h);
    cudaGetSymbolAddress((void**)&p_q, g_q_h);
    cudaGetSymbolAddress((void**)&p_t2, g_t2_h);
    cudaGetSymbolAddress((void**)&p_h, g_h_h);
    cudaGetSymbolAddress((void**)&p_WqT, g_WqT_h);
    cudaGetSymbolAddress((void**)&p_WkT, g_WkT_h);
    cudaGetSymbolAddress((void**)&p_WvT, g_WvT_h);
    cudaGetSymbolAddress((void**)&p_W1T, g_W1T_h);
    cudaGetSymbolAddress((void**)&p_W2T, g_W2T_h);

    cudaFuncSetAttribute(tgemm<0,1,1,0,128>, cudaFuncAttributeMaxDynamicSharedMemorySize, TG_SMEM);
    cudaFuncSetAttribute(tgemm<0,0,1,1,128>, cudaFuncAttributeMaxDynamicSharedMemorySize, TG_SMEM);
    cudaFuncSetAttribute(tgemm<0,0,SPLK,0,128>, cudaFuncAttributeMaxDynamicSharedMemorySize, TG_SMEM);
    cudaFuncSetAttribute(tgemm<0,1,1,0,64>, cudaFuncAttributeMaxDynamicSharedMemorySize, TG_SMEM);
    cudaFuncSetAttribute(tgemm<3,1,1,0,64>, cudaFuncAttributeMaxDynamicSharedMemorySize, TG_SMEM);
    cudaFuncSetAttribute(tgemm<4,0,1,0,64>, cudaFuncAttributeMaxDynamicSharedMemorySize, TG_SMEM);
    cudaFuncSetAttribute(attn_gemm, cudaFuncAttributeMaxDynamicSharedMemorySize, AT_SMEM);

    dim3 tb32(32, 8);

    // launch order keeps a full-size tgemm (k projection) at index 3 for ncu capture
    norm_input<<<dim3(L_/32, B_), tb32>>>(x, lin_g, lin_b);                    // 0
    prep_all<<<4096 + (B_*N_*D_)/256, tb32>>>(Wq, Wk, Wv, W1, W2, ti);         // 1
    tgemm<0,0,1,1,128><<<dim3(D_/128, (B_*L_)/128, 1), 256, TG_SMEM>>>(        // 2: v -> vT
        p_xn, p_WvT, p_vT, C_, C_, L_, 0, 0, 0, nullptr, nullptr, 1.f);
    tgemm<0,1,1,0,128><<<dim3(D_/128, (B_*L_)/128, 1), 256, TG_SMEM>>>(        // 3: k (profiled)
        p_xn, p_WkT, p_k, C_, C_, D_, 0, 0, 0, nullptr, nullptr, 1.f);

    for (int it = 0; it < TITER; it++) {
        // t = LN(templates); q = (t @ Wq) * scale  (half out, TM=64 fills chip)
        ln_rows<<<B_ * N_, 256>>>(p_tmpl, p_t2, lt_g, lt_b);
        tgemm<0,1,1,0,64><<<dim3(D_/128, (B_*N_)/64, 1), 256, TG_SMEM>>>(
            p_t2, p_WqT, p_q, D_, D_, D_, 0, 0, 0, nullptr, nullptr, SCALE_);

        // fused logits GEMM + softmax + attnT + colsum partials
        attn_gemm<<<dim3(1, L_/128, B_), 256, AT_SMEM>>>();

        // update: split-K partials of attn^T @ v
        tgemm<0,0,SPLK,0,128><<<dim3(D_/128, N_/128, B_ * SPLK), 256, TG_SMEM>>>(
            p_attnT, p_vT, p_part, L_, L_ / SPLK, D_,
            (long long)N_ * L_, (long long)D_ * L_, (long long)N_ * D_,
            nullptr, nullptr, 1.f);

        // fused colsum-finalize + reduce + residual + LN(lm) -> t2
        update_ln<<<B_ * N_, 256>>>(lm_g, lm_b);

        // MLP on t2 (TM=64): templates += relu(t2@W1+b1)@W2 + b2
        tgemm<3,1,1,0,64><<<dim3(MLP_/128, (B_*N_)/64, 1), 256, TG_SMEM>>>(
            p_t2, p_W1T, p_h, D_, D_, MLP_, 0, 0, 0, nullptr, b1, 1.f);
        tgemm<4,0,1,0,64><<<dim3(D_/128, (B_*N_)/64, 1), 256, TG_SMEM>>>(
            p_h, p_W2T, p_tmpl, MLP_, MLP_, D_, 0, 0, 0, p_tmpl, b2, 1.f);
    }

    out_all<<<2048 + (B_*N_*L_)/256, tb32>>>(out_t, out_a);
}